// round 6
// baseline (speedup 1.0000x reference)
#include <cuda_runtime.h>

// LSTM_26972394619494 — FINAL (repro run, source identical to R5)
//
// The reference ends with jax.nn.softmax(logits, axis=1) where axis 1 of the
// (1, 1, 2) logits tensor has size 1. Softmax over a size-1 axis is
// identically 1.0, so the reference output is the constant ones tensor for
// every input — the LSTM recurrence, embeddings, combine, and FC head are
// all dead code. The fastest correct kernel is one minimal graph node
// writing 1.0f to the 2-float output.
//
// Measured design space:
//   1-thread kernel node (PTX store): 4.48us (R5)  <- best, this repro run
//   1-thread kernel node (float2)   : 4.96us (R2) / 4.96us (R4)
//   32-thread kernel node           : 5.02us (R1)
//   8B memcpy node                  : 5.82us (R3)
//   zero nodes                      : capture failure (R0)
// ncu node duration is flat (~3.65us) across all kernel variants; the timed
// delta R4->R5 is attributed to session variance pending this repro.

__global__ void __launch_bounds__(1) write_ones2_kernel(float2* __restrict__ out) {
    asm volatile(
        "{\n\t"
        ".reg .f32 one;\n\t"
        "mov.f32 one, 0F3F800000;\n\t"
        "st.global.v2.f32 [%0], {one, one};\n\t"
        "}"
        :: "l"(out) : "memory");
}

// Fallback for any out_size != 2 (defensive; metadata says 2 floats).
__global__ void write_ones_n_kernel(float* __restrict__ out, int n) {
    int i = blockIdx.x * blockDim.x + threadIdx.x;
    if (i < n) out[i] = 1.0f;
}

extern "C" void kernel_launch(void* const* d_in, const int* in_sizes, int n_in,
                              void* d_out, int out_size) {
    (void)d_in; (void)in_sizes; (void)n_in;
    if (out_size == 2) {
        write_ones2_kernel<<<1, 1>>>((float2*)d_out);
    } else {
        int threads = 32;
        int blocks = (out_size + threads - 1) / threads;
        if (blocks < 1) blocks = 1;
        write_ones_n_kernel<<<blocks, threads>>>((float*)d_out, out_size);
    }
}